// round 16
// baseline (speedup 1.0000x reference)
#include <cuda_runtime.h>
#include <cuda_fp16.h>
#include <cuda_fp8.h>
#include <cstdint>

#define B_ 4096
#define N_ 32768
#define D_ 1024
#define BM 256
#define BN 128
#define NSTAGE 4
#define KSLABS 8                // 1024 fp8 bytes / 128 per slab
#define A_SLAB 32768            // 256 rows * 128B
#define B_SLAB 16384            // 128 rows * 128B
#define STAGE_BYTES (A_SLAB + B_SLAB)   // 48KB
#define NBLKS 1024              // 32-key blocks per row
#define MARGIN 0.010f
#define QSCALE 32.0f
#define INV_S (1.0f/QSCALE)
#define INV_S2 (1.0f/(QSCALE*QSCALE))

// ------------------------- scratch (no allocations allowed) -------------------------
__device__ float         g_qn[(size_t)B_*D_];     // normalized Q fp32 (refinement)
__device__ unsigned char g_qsw[(size_t)B_*D_];    // Q e4m3, slab-contiguous SW128 layout
__device__ unsigned char g_ksw[(size_t)N_*D_];    // K e4m3, slab-contiguous SW128 layout
__device__ float         g_kinv[N_];              // 1/||k||
__device__ float4        g_h4[D_/4];              // h_d = sum_n k_d * dk_d
__device__ float4        g_u4[D_/4];              // u_d = sum_n dk_d^2
__device__ float4        g_w4[D_/4];              // w_d = sum_n khat_d^2
__device__ float         g_corr[B_];              // per-row sumsq quantization correction
__device__ float4        g_blk[(size_t)B_*NBLKS]; // per 32-key block: (max, m2|idx, sum, sumsq)
__device__ float         g_var[B_];

// ------------------------- helpers -------------------------
__device__ __forceinline__ uint32_t cvta_s(const void* p) {
    return (uint32_t)__cvta_generic_to_shared(p);
}
__device__ __forceinline__ void cp_async16(uint32_t dst, const void* src) {
    asm volatile("cp.async.cg.shared.global [%0], [%1], 16;\n" :: "r"(dst), "l"(src));
}
__device__ __forceinline__ void cp_commit() {
    asm volatile("cp.async.commit_group;\n" ::: "memory");
}
template <int NN> __device__ __forceinline__ void cp_wait() {
    asm volatile("cp.async.wait_group %0;\n" :: "n"(NN) : "memory");
}
__device__ __forceinline__ void ldsm4(uint32_t& r0, uint32_t& r1, uint32_t& r2, uint32_t& r3, uint32_t a) {
    asm volatile("ldmatrix.sync.aligned.m8n8.x4.shared.b16 {%0,%1,%2,%3},[%4];\n"
        : "=r"(r0), "=r"(r1), "=r"(r2), "=r"(r3) : "r"(a));
}
__device__ __forceinline__ void mma_fp8(float* c, const uint32_t* a, const uint32_t* b) {
    asm volatile("mma.sync.aligned.m16n8k32.row.col.f32.e4m3.e4m3.f32 "
        "{%0,%1,%2,%3},{%4,%5,%6,%7},{%8,%9},{%0,%1,%2,%3};\n"
        : "+f"(c[0]), "+f"(c[1]), "+f"(c[2]), "+f"(c[3])
        : "r"(a[0]), "r"(a[1]), "r"(a[2]), "r"(a[3]), "r"(b[0]), "r"(b[1]));
}
__device__ __forceinline__ uint32_t swz(uint32_t r, uint32_t cByte) {
    return r * 128u + (cByte ^ ((r & 7u) << 4));
}
// quantize 4 normalized floats -> packed e4m3 + dequant values (normalized units)
__device__ __forceinline__ uint32_t quant4r(float4 o, float4& dq) {
    __nv_fp8x2_storage_t a01 = __nv_cvt_float2_to_fp8x2(
        make_float2(o.x * QSCALE, o.y * QSCALE), __NV_SATFINITE, __NV_E4M3);
    __nv_fp8x2_storage_t a23 = __nv_cvt_float2_to_fp8x2(
        make_float2(o.z * QSCALE, o.w * QSCALE), __NV_SATFINITE, __NV_E4M3);
    __half2_raw h01 = __nv_cvt_fp8x2_to_halfraw2(a01, __NV_E4M3);
    __half2_raw h23 = __nv_cvt_fp8x2_to_halfraw2(a23, __NV_E4M3);
    float2 d01 = __half22float2(*(__half2*)&h01);
    float2 d23 = __half22float2(*(__half2*)&h23);
    dq.x = d01.x * INV_S; dq.y = d01.y * INV_S;
    dq.z = d23.x * INV_S; dq.w = d23.y * INV_S;
    return (uint32_t)a01 | ((uint32_t)a23 << 16);
}

// ------------------------- zero the gram-diag accumulators (graph determinism!) -------------------------
__global__ void zero_huw() {
    int t = threadIdx.x;                 // 256 threads
    g_h4[t] = make_float4(0.f, 0.f, 0.f, 0.f);
    g_u4[t] = make_float4(0.f, 0.f, 0.f, 0.f);
    g_w4[t] = make_float4(0.f, 0.f, 0.f, 0.f);
}

// ------------------------- normalize K + fp8 quantize (SW128 slab layout) -------------------------
__global__ void norm_rows_k(const float* __restrict__ x) {
    int row = blockIdx.x, tid = threadIdx.x;
    const float4* xp = (const float4*)(x + (size_t)row * D_);
    float4 a = xp[tid];
    float ss = a.x*a.x + a.y*a.y + a.z*a.z + a.w*a.w;
    __shared__ float sh[256];
    sh[tid] = ss; __syncthreads();
    for (int s = 128; s > 0; s >>= 1) { if (tid < s) sh[tid] += sh[tid+s]; __syncthreads(); }
    float inv = 1.0f / fmaxf(sqrtf(sh[0]), 1e-12f);
    if (tid == 0) g_kinv[row] = inv;
    float4 o; o.x = a.x*inv; o.y = a.y*inv; o.z = a.z*inv; o.w = a.w*inv;
    float4 dq;
    uint32_t pk = quant4r(o, dq);
    int nt = row >> 7, r_in = row & 127;
    int kslab = tid >> 5;
    uint32_t b = (uint32_t)((tid & 31) * 4);
    uint32_t off = (uint32_t)r_in * 128u + (((b & ~15u) ^ (((uint32_t)(r_in & 7) << 4))) | (b & 15u));
    *(uint32_t*)(g_ksw + (size_t)(nt * KSLABS + kslab) * B_SLAB + off) = pk;
}

// ------------------------- gram diagonals over keys: h, u, w -------------------------
__global__ __launch_bounds__(256) void gram_h(const float* __restrict__ keys) {
    const int tid = threadIdx.x;
    const int r0 = blockIdx.x * (N_ / 256);          // 256 blocks x 128 rows
    float4 h = make_float4(0.f, 0.f, 0.f, 0.f);
    float4 u = make_float4(0.f, 0.f, 0.f, 0.f);
    float4 w = make_float4(0.f, 0.f, 0.f, 0.f);
    #pragma unroll 1
    for (int i = 0; i < N_ / 256; ++i) {
        int row = r0 + i;
        float inv = g_kinv[row];
        float4 a = ((const float4*)(keys + (size_t)row * D_))[tid];
        float4 o; o.x = a.x*inv; o.y = a.y*inv; o.z = a.z*inv; o.w = a.w*inv;
        float4 dq;
        quant4r(o, dq);
        float rx = dq.x - o.x, ry = dq.y - o.y, rz = dq.z - o.z, rw = dq.w - o.w;
        h.x = fmaf(o.x, rx, h.x); h.y = fmaf(o.y, ry, h.y);
        h.z = fmaf(o.z, rz, h.z); h.w = fmaf(o.w, rw, h.w);
        u.x = fmaf(rx, rx, u.x); u.y = fmaf(ry, ry, u.y);
        u.z = fmaf(rz, rz, u.z); u.w = fmaf(rw, rw, u.w);
        w.x = fmaf(dq.x, dq.x, w.x); w.y = fmaf(dq.y, dq.y, w.y);
        w.z = fmaf(dq.z, dq.z, w.z); w.w = fmaf(dq.w, dq.w, w.w);
    }
    float* hp = (float*)g_h4; float* up = (float*)g_u4; float* wp = (float*)g_w4;
    atomicAdd(&hp[4*tid+0], h.x); atomicAdd(&hp[4*tid+1], h.y);
    atomicAdd(&hp[4*tid+2], h.z); atomicAdd(&hp[4*tid+3], h.w);
    atomicAdd(&up[4*tid+0], u.x); atomicAdd(&up[4*tid+1], u.y);
    atomicAdd(&up[4*tid+2], u.z); atomicAdd(&up[4*tid+3], u.w);
    atomicAdd(&wp[4*tid+0], w.x); atomicAdd(&wp[4*tid+1], w.y);
    atomicAdd(&wp[4*tid+2], w.z); atomicAdd(&wp[4*tid+3], w.w);
}

// ------------------------- normalize Q + quantize + per-row correction -------------------------
__global__ void norm_rows_q(const float* __restrict__ x) {
    int row = blockIdx.x, tid = threadIdx.x;
    const float4* xp = (const float4*)(x + (size_t)row * D_);
    float4 a = xp[tid];
    float ss = a.x*a.x + a.y*a.y + a.z*a.z + a.w*a.w;
    __shared__ float sh[256];
    sh[tid] = ss; __syncthreads();
    for (int s = 128; s > 0; s >>= 1) { if (tid < s) sh[tid] += sh[tid+s]; __syncthreads(); }
    float inv = 1.0f / fmaxf(sqrtf(sh[0]), 1e-12f);
    float4 o; o.x = a.x*inv; o.y = a.y*inv; o.z = a.z*inv; o.w = a.w*inv;
    ((float4*)(g_qn + (size_t)row * D_))[tid] = o;
    float4 dq;
    uint32_t pk = quant4r(o, dq);
    // correction: sum_d [ q^2 (2h + u) + (dq-q) w (2q + (dq-q)) ]
    float4 h = g_h4[tid], u = g_u4[tid], w = g_w4[tid];
    float rx = dq.x - o.x, ry = dq.y - o.y, rz = dq.z - o.z, rw = dq.w - o.w;
    float c =
        o.x*o.x*(2.f*h.x + u.x) + rx*w.x*(2.f*o.x + rx) +
        o.y*o.y*(2.f*h.y + u.y) + ry*w.y*(2.f*o.y + ry) +
        o.z*o.z*(2.f*h.z + u.z) + rz*w.z*(2.f*o.z + rz) +
        o.w*o.w*(2.f*h.w + u.w) + rw*w.w*(2.f*o.w + rw);
    __syncthreads();
    sh[tid] = c; __syncthreads();
    for (int s = 128; s > 0; s >>= 1) { if (tid < s) sh[tid] += sh[tid+s]; __syncthreads(); }
    if (tid == 0) g_corr[row] = sh[0];
    int mt = row >> 8, r_in = row & 255;
    int kslab = tid >> 5;
    uint32_t b = (uint32_t)((tid & 31) * 4);
    uint32_t off = (uint32_t)r_in * 128u + (((b & ~15u) ^ (((uint32_t)(r_in & 7) << 4))) | (b & 15u));
    *(uint32_t*)(g_qsw + (size_t)(mt * KSLABS + kslab) * A_SLAB + off) = pk;
}

// ------------------------- GEMM: e4m3 mma.sync k32, 256x128 tile, 16 warps -------------------------
__global__ __launch_bounds__(512, 1) void sim_gemm() {
    extern __shared__ __align__(16) unsigned char smraw[];   // NSTAGE * 48KB

    const int tid = threadIdx.x;
    const int lane = tid & 31, warp = tid >> 5;
    const int wr = warp >> 2;            // 4 warp-rows of 64
    const int wc = warp & 3;             // 4 warp-cols of 32
    const int wm = wr * 64;
    const int mt = blockIdx.x;
    const int nt = blockIdx.y;

    const unsigned char* qbase = g_qsw + (size_t)mt * KSLABS * A_SLAB;
    const unsigned char* kbase = g_ksw + (size_t)nt * KSLABS * B_SLAB;
    const uint32_t sbase = cvta_s(smraw);

    float acc[4][4][4];
    #pragma unroll
    for (int i = 0; i < 4; i++)
        #pragma unroll
        for (int j = 0; j < 4; j++)
            #pragma unroll
            for (int k = 0; k < 4; k++) acc[i][j][k] = 0.f;

    // prologue: slabs 0..2 into stages 0..2
    #pragma unroll
    for (int s = 0; s < NSTAGE - 1; ++s) {
        uint32_t st = sbase + s * STAGE_BYTES;
        #pragma unroll
        for (int i = 0; i < 4; ++i) {
            uint32_t o = (uint32_t)(i * 8192 + tid * 16);
            cp_async16(st + o, qbase + (size_t)s * A_SLAB + o);
        }
        #pragma unroll
        for (int i = 0; i < 2; ++i) {
            uint32_t o = (uint32_t)(i * 8192 + tid * 16);
            cp_async16(st + A_SLAB + o, kbase + (size_t)s * B_SLAB + o);
        }
        cp_commit();
    }

    const uint32_t rsel = lane & 15;
    const uint32_t cbase = (uint32_t)((lane >> 4) << 4);   // 0 or 16 bytes

    #pragma unroll 1
    for (int t = 0; t < KSLABS; ++t) {
        cp_wait<NSTAGE - 2>();
        __syncthreads();
        if (t + NSTAGE - 1 < KSLABS) {
            int s2 = (t + NSTAGE - 1) & (NSTAGE - 1);
            uint32_t st = sbase + s2 * STAGE_BYTES;
            #pragma unroll
            for (int i = 0; i < 4; ++i) {
                uint32_t o = (uint32_t)(i * 8192 + tid * 16);
                cp_async16(st + o, qbase + (size_t)(t + NSTAGE - 1) * A_SLAB + o);
            }
            #pragma unroll
            for (int i = 0; i < 2; ++i) {
                uint32_t o = (uint32_t)(i * 8192 + tid * 16);
                cp_async16(st + A_SLAB + o, kbase + (size_t)(t + NSTAGE - 1) * B_SLAB + o);
            }
        }
        cp_commit();

        uint32_t sA = sbase + (t & (NSTAGE - 1)) * STAGE_BYTES;
        uint32_t sB = sA + A_SLAB;
        #pragma unroll
        for (int kk = 0; kk < 4; ++kk) {               // 4 x k=32B per 128B slab
            uint32_t cByte = (uint32_t)(kk * 32) + cbase;
            uint32_t af[4][4], bf[4][2];
            #pragma unroll
            for (int mi = 0; mi < 4; ++mi)
                ldsm4(af[mi][0], af[mi][1], af[mi][2], af[mi][3],
                      sA + swz(wm + mi * 16 + rsel, cByte));
            #pragma unroll
            for (int nh = 0; nh < 2; ++nh) {
                uint32_t r0, r1, r2, r3;
                ldsm4(r0, r1, r2, r3, sB + swz(wc * 32 + nh * 16 + rsel, cByte));
                bf[nh*2+0][0] = r0; bf[nh*2+0][1] = r2;
                bf[nh*2+1][0] = r1; bf[nh*2+1][1] = r3;
            }
            #pragma unroll
            for (int mi = 0; mi < 4; ++mi)
                #pragma unroll
                for (int ni = 0; ni < 4; ++ni)
                    mma_fp8(acc[mi][ni], af[mi], bf[ni]);
        }
    }

    // register epilogue: per (row, 32-col warp tile) -> (max, runnerup|idx, sum, sumsq)
    const int rq = lane >> 2;            // row within 8
    const int lq = lane & 3;             // col quarter
    #pragma unroll
    for (int mi = 0; mi < 4; ++mi) {
        #pragma unroll
        for (int r = 0; r < 2; ++r) {
            float m1 = -1e30f, m2 = -1e30f; int i1 = 0;
            float s = 0.f, q = 0.f;
            #pragma unroll
            for (int ni = 0; ni < 4; ++ni) {
                float vx = acc[mi][ni][r*2]   * INV_S2;
                float vy = acc[mi][ni][r*2+1] * INV_S2;
                int c = ni * 8 + lq * 2;
                if (vx > m1) { m2 = m1; m1 = vx; i1 = c; } else m2 = fmaxf(m2, vx);
                if (vy > m1) { m2 = m1; m1 = vy; i1 = c + 1; } else m2 = fmaxf(m2, vy);
                s += vx + vy;
                q = fmaf(vx, vx, q); q = fmaf(vy, vy, q);
            }
            #pragma unroll
            for (int d = 1; d <= 2; d <<= 1) {
                float om1 = __shfl_xor_sync(0xffffffffu, m1, d, 4);
                float om2 = __shfl_xor_sync(0xffffffffu, m2, d, 4);
                int   oi  = __shfl_xor_sync(0xffffffffu, i1, d, 4);
                if (om1 > m1) { m2 = fmaxf(m1, om2); m1 = om1; i1 = oi; }
                else          { m2 = fmaxf(m2, om1); }
                s += __shfl_xor_sync(0xffffffffu, s, d, 4);
                q += __shfl_xor_sync(0xffffffffu, q, d, 4);
            }
            if (lq == 0) {
                int row = mt * BM + wm + mi * 16 + rq + r * 8;
                uint32_t pb = (__float_as_uint(m2) & ~31u) | (uint32_t)i1;
                g_blk[(size_t)row * NBLKS + nt * 4 + wc] =
                    make_float4(m1, __uint_as_float(pb), s, q);
            }
        }
    }
}

// ------------------------- finalize: warp per row, key-granular refinement -------------------------
__global__ __launch_bounds__(256) void finalize_rows(const float* __restrict__ keys,
                                                     const float* __restrict__ values,
                                                     float* __restrict__ out) {
    const int wid = threadIdx.x >> 5, lane = threadIdx.x & 31;
    const int row = blockIdx.x * 8 + wid;
    __shared__ int klist[8][16];
    __shared__ int blist[8][4];
    __shared__ int kcnt[8], bcnt[8];

    const float4* bp = (const float4*)g_blk + (size_t)row * NBLKS;
    float lm = -1e30f, s = 0.f, q2 = 0.f;
    #pragma unroll
    for (int i = 0; i < 32; ++i) {
        float4 b = bp[i * 32 + lane];
        lm = fmaxf(lm, b.x); s += b.z; q2 += b.w;
    }
    #pragma unroll
    for (int d = 16; d > 0; d >>= 1) {
        lm = fmaxf(lm, __shfl_xor_sync(0xffffffffu, lm, d));
        s  += __shfl_xor_sync(0xffffffffu, s,  d);
        q2 += __shfl_xor_sync(0xffffffffu, q2, d);
    }
    if (lane == 0) { kcnt[wid] = 0; bcnt[wid] = 0; }
    __syncwarp();
    float thr = lm - MARGIN;
    #pragma unroll
    for (int i = 0; i < 32; ++i) {
        float4 b = bp[i * 32 + lane];
        if (b.x >= thr) {
            int blk = i * 32 + lane;
            uint32_t pb = __float_as_uint(b.y);
            int p = atomicAdd(&kcnt[wid], 1);
            if (p < 16) klist[wid][p] = blk * 32 + (int)(pb & 31u);
            if (b.y >= thr) {             // runner-up near max -> refine whole block
                int p2 = atomicAdd(&bcnt[wid], 1);
                if (p2 < 4) blist[wid][p2] = blk;
            }
        }
    }
    __syncwarp();
    int nk = min(kcnt[wid], 16), nb = min(bcnt[wid], 4);

    float bv = -1e30f; int bi = 0x7fffffff;
    const float4* qp = (const float4*)(g_qn + (size_t)row * D_);
    for (int ci = 0; ci < nk; ++ci) {
        int n = klist[wid][ci];
        const float4* kp = (const float4*)(keys + (size_t)n * D_);
        float a0 = 0.f;
        #pragma unroll
        for (int j = 0; j < 8; ++j) {
            float4 qa = qp[j * 32 + lane], kb = kp[j * 32 + lane];
            a0 += qa.x*kb.x + qa.y*kb.y + qa.z*kb.z + qa.w*kb.w;
        }
        #pragma unroll
        for (int d = 16; d > 0; d >>= 1) a0 += __shfl_xor_sync(0xffffffffu, a0, d);
        float sv = a0 * g_kinv[n];
        if (sv > bv || (sv == bv && n < bi)) { bv = sv; bi = n; }
    }
    for (int ci = 0; ci < nb; ++ci) {
        int n0 = blist[wid][ci] * 32;
        #pragma unroll 1
        for (int kx = 0; kx < 32; ++kx) {
            int n = n0 + kx;
            const float4* kp = (const float4*)(keys + (size_t)n * D_);
            float a0 = 0.f;
            #pragma unroll
            for (int j = 0; j < 8; ++j) {
                float4 qa = qp[j * 32 + lane], kb = kp[j * 32 + lane];
                a0 += qa.x*kb.x + qa.y*kb.y + qa.z*kb.z + qa.w*kb.w;
            }
            #pragma unroll
            for (int d = 16; d > 0; d >>= 1) a0 += __shfl_xor_sync(0xffffffffu, a0, d);
            float sv = a0 * g_kinv[n];
            if (sv > bv || (sv == bv && n < bi)) { bv = sv; bi = n; }
        }
    }

    const float4* vp = (const float4*)(values + (size_t)bi * D_);
    float4* op = (float4*)(out + (size_t)row * D_);
    #pragma unroll
    for (int j = 0; j < 8; ++j) op[j * 32 + lane] = vp[j * 32 + lane];

    if (lane == 0) {
        // exact diagonal quantization correction:
        //   sum sim_hat^2 - sum sim^2 = 2 q^T H q + q^T U q + 2 dq^T Ghat q + dq^T Ghat dq (diag parts)
        g_var[row] = (q2 - g_corr[row] - s * s * (1.0f / N_)) * (1.0f / (N_ - 1));
    }
}

__global__ void var_mean(float* __restrict__ out, int out_size) {
    __shared__ float sh[256];
    int tid = threadIdx.x;
    float a = 0.f;
    for (int i = tid; i < B_; i += 256) a += g_var[i];
    sh[tid] = a; __syncthreads();
    for (int s = 128; s > 0; s >>= 1) { if (tid < s) sh[tid] += sh[tid + s]; __syncthreads(); }
    if (tid == 0) {
        long long base = (long long)B_ * D_;
        if (out_size > base) out[base] = sh[0] * (1.0f / B_);
    }
}

// ------------------------- launch -------------------------
extern "C" void kernel_launch(void* const* d_in, const int* in_sizes, int n_in,
                              void* d_out, int out_size) {
    const float* q = (const float*)d_in[0];
    const float* k = (const float*)d_in[1];
    const float* v = (const float*)d_in[2];
    float* out = (float*)d_out;

    const int dyn = NSTAGE * STAGE_BYTES;   // 196608
    cudaFuncSetAttribute(sim_gemm, cudaFuncAttributeMaxDynamicSharedMemorySize, dyn);

    zero_huw<<<1, 256>>>();                 // must re-zero every replay (atomics below)
    norm_rows_k<<<N_, 256>>>(k);            // writes g_kinv + k-hat layout
    gram_h<<<256, 256>>>(k);                // h,u,w diagonals (needs g_kinv)
    norm_rows_q<<<B_, 256>>>(q);            // writes q layout + per-row correction (needs h,u,w)
    dim3 g(B_ / BM, N_ / BN);               // m fastest -> K-tile reuse through L2
    sim_gemm<<<g, 512, dyn>>>();
    finalize_rows<<<B_ / 8, 256>>>(k, v, out);
    var_mean<<<1, 256>>>(out, out_size);
}